// round 2
// baseline (speedup 1.0000x reference)
#include <cuda_runtime.h>

#define BN 64
#define TT 12
#define NN 716
#define DD 64
#define EE 32
#define TN 8592            // TT*NN
#define XELEMS 35192832    // BN*TN*DD

#define K1_STAGE 64
#define K1_STAGES 4
#define K1_CHUNK (K1_STAGE*K1_STAGES)                     // 256
#define K1_BLOCKS_PER_B ((TN + K1_CHUNK - 1)/K1_CHUNK)    // 34
#define K3_BLOCKS_PER_B 24
#define K3_CHUNK 358                                      // 24*358 == 8592

__device__ float g_bufA[XELEMS];
__device__ float g_bufB[XELEMS];
__device__ float g_assign[(size_t)BN*TN*EE];  // 17.6M
__device__ float g_hf[BN*EE*DD];
__device__ float g_ho[BN*EE*DD];

__global__ __launch_bounds__(256) void k_zero_hf(float* hf) {
    int i = blockIdx.x*256 + threadIdx.x;
    if (i < BN*EE*DD) hf[i] = 0.f;
}

// K1: assign = softmax(x @ edge_clf); hf[b] += assign^T @ x   (block-local regs + final atomics)
__global__ __launch_bounds__(256) void k_assign_hf(
    const float* __restrict__ x, const float* __restrict__ edge_clf,
    float* __restrict__ assign, float* __restrict__ hf)
{
    __shared__ float ec[64][32];
    __shared__ float xs[64][64];
    __shared__ float as[64][32];
    int tid = threadIdx.x;
    int b = blockIdx.x;
    int r0base = blockIdx.y * K1_CHUNK;
    int lane = tid & 31, warp = tid >> 5;
    int e_own = tid >> 3;
    int dbase = (tid & 7) * 8;

    for (int i = tid; i < 64*32; i += 256) ec[i>>5][i&31] = edge_clf[i];

    float acc[8];
    #pragma unroll
    for (int j = 0; j < 8; j++) acc[j] = 0.f;

    const float* xb = x + (size_t)b*TN*DD;

    for (int s = 0; s < K1_STAGES; s++) {
        int r0 = r0base + s*K1_STAGE;
        __syncthreads();
        // load 64 rows of x (zero-padded past TN)
        #pragma unroll
        for (int p = 0; p < 4; p++) {
            int row = p*16 + (tid >> 4);
            int q = (tid & 15) * 4;
            int gr = r0 + row;
            float4 v = make_float4(0.f,0.f,0.f,0.f);
            if (gr < TN) v = *(const float4*)(xb + (size_t)gr*DD + q);
            *(float4*)(&xs[row][q]) = v;
        }
        __syncthreads();
        // logits + warp softmax: warp w handles rows it*8+w, lane = e
        #pragma unroll
        for (int it = 0; it < 8; it++) {
            int r = it*8 + warp;
            int gr = r0 + r;
            float v = 0.f;
            #pragma unroll
            for (int k = 0; k < 64; k++) v += xs[r][k] * ec[k][lane];
            float m = v;
            #pragma unroll
            for (int o = 16; o; o >>= 1) m = fmaxf(m, __shfl_xor_sync(0xffffffffu, m, o));
            float ex = __expf(v - m);
            float sm = ex;
            #pragma unroll
            for (int o = 16; o; o >>= 1) sm += __shfl_xor_sync(0xffffffffu, sm, o);
            float p = ex / sm;
            bool valid = (gr < TN);
            as[r][lane] = valid ? p : 0.f;
            if (valid) assign[((size_t)b*TN + gr)*EE + lane] = p;
        }
        __syncthreads();
        // acc[e_own][dbase..dbase+8) += assign^T @ x  over 64 rows
        #pragma unroll 4
        for (int r = 0; r < 64; r++) {
            float a = as[r][e_own];
            #pragma unroll
            for (int j = 0; j < 8; j++) acc[j] += a * xs[r][dbase + j];
        }
    }
    float* hb = hf + b*EE*DD + e_own*DD + dbase;
    #pragma unroll
    for (int j = 0; j < 8; j++) atomicAdd(hb + j, acc[j]);
}

// K2: ho = relu(edge_map @ hf) + hf      (one block per batch)
__global__ __launch_bounds__(256) void k_edge_mix(
    const float* __restrict__ hf, const float* __restrict__ edge_map,
    float* __restrict__ ho)
{
    __shared__ float hfs[32][64];
    __shared__ float em[32][32];
    int tid = threadIdx.x;
    int b = blockIdx.x;
    const float* hb = hf + b*EE*DD;
    for (int i = tid; i < 2048; i += 256) hfs[i>>6][i&63] = hb[i];
    for (int i = tid; i < 1024; i += 256) em[i>>5][i&31] = edge_map[i];
    __syncthreads();
    int e = tid >> 3, dbase = (tid & 7) * 8;
    float o[8];
    #pragma unroll
    for (int j = 0; j < 8; j++) o[j] = 0.f;
    #pragma unroll
    for (int f = 0; f < 32; f++) {
        float w = em[e][f];
        #pragma unroll
        for (int j = 0; j < 8; j++) o[j] += w * hfs[f][dbase + j];
    }
    float* ob = ho + b*EE*DD + e*DD + dbase;
    #pragma unroll
    for (int j = 0; j < 8; j++) ob[j] = fmaxf(o[j], 0.f) + hfs[e][dbase + j];
}

// K3: fused STGCN GEMVs + gate + LN1, hyper y + LN2, average. One warp per row.
__global__ __launch_bounds__(256) void k_fused_out(
    const float* __restrict__ x,
    const float* __restrict__ W1, const float* __restrict__ b1,
    const float* __restrict__ W2, const float* __restrict__ b2,
    const float* __restrict__ ln1g, const float* __restrict__ ln1b,
    const float* __restrict__ ln2g, const float* __restrict__ ln2b,
    const float* __restrict__ assign, const float* __restrict__ ho,
    float* __restrict__ out)
{
    __shared__ float w1s[64][64];
    __shared__ float w2s[64][64];
    __shared__ float hos[32][64];
    __shared__ float prm[6][64];
    __shared__ float xms[8][64];
    int tid = threadIdx.x;
    int b = blockIdx.x;
    for (int i = tid; i < 4096; i += 256) { w1s[i>>6][i&63] = W1[i]; w2s[i>>6][i&63] = W2[i]; }
    for (int i = tid; i < 2048; i += 256) hos[i>>6][i&63] = ho[b*EE*DD + i];
    if (tid < 64) {
        prm[0][tid] = b1[tid];   prm[1][tid] = b2[tid];
        prm[2][tid] = ln1g[tid]; prm[3][tid] = ln1b[tid];
        prm[4][tid] = ln2g[tid]; prm[5][tid] = ln2b[tid];
    }
    __syncthreads();

    int lane = tid & 31, warp = tid >> 5;
    int d0 = lane, d1 = lane + 32;
    int rstart = blockIdx.y * K3_CHUNK;
    int rend = rstart + K3_CHUNK;
    const float* xb = x + (size_t)b*TN*DD;
    const float* ab = assign + (size_t)b*TN*EE;
    float* ob = out + (size_t)b*TN*DD;

    for (int r = rstart + warp; r < rend; r += 8) {
        const float* xr = xb + (size_t)r*DD;
        float xv0 = xr[d0], xv1 = xr[d1];
        float xp0 = 0.f, xp1 = 0.f;
        if (r >= NN) { xp0 = xr[d0 - NN*DD]; xp1 = xr[d1 - NN*DD]; }
        float m0 = 0.5f*(xv0 + xp0), m1 = 0.5f*(xv1 + xp1);
        xms[warp][d0] = m0; xms[warp][d1] = m1;
        float av = ab[(size_t)r*EE + lane];
        __syncwarp();

        float g1a = prm[0][d0], g1b = prm[0][d1];
        float g2a = prm[1][d0], g2b = prm[1][d1];
        #pragma unroll
        for (int k = 0; k < 64; k++) {
            float m = xms[warp][k];
            g1a += m * w1s[k][d0]; g1b += m * w1s[k][d1];
            g2a += m * w2s[k][d0]; g2b += m * w2s[k][d1];
        }
        float f0 = fmaxf(g1a*g2a, 0.f) + g1a + xv0;
        float f1 = fmaxf(g1b*g2b, 0.f) + g1b + xv1;
        // LN1 over 64 values (2 per lane)
        float s  = f0 + f1;
        float s2 = f0*f0 + f1*f1;
        #pragma unroll
        for (int o = 16; o; o >>= 1) {
            s  += __shfl_xor_sync(0xffffffffu, s,  o);
            s2 += __shfl_xor_sync(0xffffffffu, s2, o);
        }
        float mu = s * (1.f/64.f);
        float var = s2 * (1.f/64.f) - mu*mu;
        float rs = rsqrtf(var + 1e-5f);
        float o1a = (f0 - mu)*rs*prm[2][d0] + prm[3][d0];
        float o1b = (f1 - mu)*rs*prm[2][d1] + prm[3][d1];

        // hyper: y = relu(assign @ ho)
        float y0 = 0.f, y1 = 0.f;
        #pragma unroll
        for (int e = 0; e < 32; e++) {
            float ae = __shfl_sync(0xffffffffu, av, e);
            y0 += ae * hos[e][d0];
            y1 += ae * hos[e][d1];
        }
        float h0 = fmaxf(y0, 0.f) + xv0;
        float h1 = fmaxf(y1, 0.f) + xv1;
        s  = h0 + h1;
        s2 = h0*h0 + h1*h1;
        #pragma unroll
        for (int o = 16; o; o >>= 1) {
            s  += __shfl_xor_sync(0xffffffffu, s,  o);
            s2 += __shfl_xor_sync(0xffffffffu, s2, o);
        }
        mu = s * (1.f/64.f);
        var = s2 * (1.f/64.f) - mu*mu;
        rs = rsqrtf(var + 1e-5f);
        float o2a = (h0 - mu)*rs*prm[4][d0] + prm[5][d0];
        float o2b = (h1 - mu)*rs*prm[4][d1] + prm[5][d1];

        ob[(size_t)r*DD + d0] = 0.5f*(o1a + o2a);
        ob[(size_t)r*DD + d1] = 0.5f*(o1b + o2b);
        __syncwarp();
    }
}

extern "C" void kernel_launch(void* const* d_in, const int* in_sizes, int n_in,
                              void* d_out, int out_size) {
    const float* x    = (const float*)d_in[0];
    const float* W1   = (const float*)d_in[1];
    const float* b1   = (const float*)d_in[2];
    const float* W2   = (const float*)d_in[3];
    const float* b2   = (const float*)d_in[4];
    const float* ln1g = (const float*)d_in[5];
    const float* ln1b = (const float*)d_in[6];
    const float* eclf = (const float*)d_in[7];
    const float* emap = (const float*)d_in[8];
    const float* ln2g = (const float*)d_in[9];
    const float* ln2b = (const float*)d_in[10];

    float *bufA, *bufB, *assign, *hf, *ho;
    cudaGetSymbolAddress((void**)&bufA,   g_bufA);
    cudaGetSymbolAddress((void**)&bufB,   g_bufB);
    cudaGetSymbolAddress((void**)&assign, g_assign);
    cudaGetSymbolAddress((void**)&hf,     g_hf);
    cudaGetSymbolAddress((void**)&ho,     g_ho);

    const float* cur = x;
    float* outs[3] = { bufA, bufB, (float*)d_out };

    for (int i = 0; i < 3; i++) {
        k_zero_hf<<<(BN*EE*DD + 255)/256, 256>>>(hf);
        dim3 g1(BN, K1_BLOCKS_PER_B);
        k_assign_hf<<<g1, 256>>>(cur, eclf, assign, hf);
        k_edge_mix<<<BN, 256>>>(hf, emap, ho);
        dim3 g3(BN, K3_BLOCKS_PER_B);
        k_fused_out<<<g3, 256>>>(cur, W1 + i*DD*DD, b1 + i*DD, W2 + i*DD*DD, b2 + i*DD,
                                 ln1g + i*DD, ln1b + i*DD, ln2g, ln2b,
                                 assign, ho, outs[i]);
        cur = outs[i];
    }
}

// round 3
// speedup vs baseline: 1.5738x; 1.5738x over previous
#include <cuda_runtime.h>

#define BN 64
#define TT 12
#define NN 716
#define DD 64
#define EE 32
#define TN 8592            // TT*NN
#define XELEMS 35192832    // BN*TN*DD

typedef unsigned long long ull;

__device__ float g_bufA[XELEMS];
__device__ float g_bufB[XELEMS];
__device__ float g_assign[(size_t)BN*TN*EE];
__device__ float g_hf[BN*EE*DD];
__device__ float g_ho[BN*EE*DD];

__device__ __forceinline__ ull fma2(ull a, ull b, ull c) {
    ull d;
    asm("fma.rn.f32x2 %0, %1, %2, %3;" : "=l"(d) : "l"(a), "l"(b), "l"(c));
    return d;
}
__device__ __forceinline__ ull packdup(float m) {
    ull d;
    asm("mov.b64 %0, {%1, %1};" : "=l"(d) : "f"(m));
    return d;
}
__device__ __forceinline__ ull pack2(float lo, float hi) {
    ull d;
    asm("mov.b64 %0, {%1, %2};" : "=l"(d) : "f"(lo), "f"(hi));
    return d;
}
__device__ __forceinline__ void unpack2(ull v, float& lo, float& hi) {
    asm("mov.b64 {%0, %1}, %2;" : "=f"(lo), "=f"(hi) : "l"(v));
}

__global__ __launch_bounds__(256) void k_zero_hf(float* hf) {
    int i = blockIdx.x*256 + threadIdx.x;
    if (i < BN*EE*DD) hf[i] = 0.f;
}

// ============================ K1: assign + hf ============================
#define K1_STAGE 64
#define K1_STAGES 4
#define K1_CHUNK (K1_STAGE*K1_STAGES)                     // 256
#define K1_BLOCKS_PER_B ((TN + K1_CHUNK - 1)/K1_CHUNK)    // 34

__global__ __launch_bounds__(256) void k_assign_hf(
    const float* __restrict__ x, const float* __restrict__ edge_clf,
    float* __restrict__ assign, float* __restrict__ hf)
{
    __shared__ float ec4[16*32*4];   // [k4][e][kk] = ec[4k4+kk][e]
    __shared__ float xs[64][64];
    __shared__ float as[64][32];
    int tid = threadIdx.x;
    int b = blockIdx.x;
    int r0base = blockIdx.y * K1_CHUNK;
    int lane = tid & 31, warp = tid >> 5;
    int e_own = tid >> 3;
    int dbase = (tid & 7) * 8;

    for (int i = tid; i < 64*32; i += 256) {
        int k = i >> 5, e = i & 31;
        ec4[(k>>2)*128 + e*4 + (k&3)] = edge_clf[i];
    }

    float acc[8];
    #pragma unroll
    for (int j = 0; j < 8; j++) acc[j] = 0.f;

    const float* xb = x + (size_t)b*TN*DD;

    for (int s = 0; s < K1_STAGES; s++) {
        int r0 = r0base + s*K1_STAGE;
        __syncthreads();
        #pragma unroll
        for (int p = 0; p < 4; p++) {
            int row = p*16 + (tid >> 4);
            int q = (tid & 15) * 4;
            int gr = r0 + row;
            float4 v = make_float4(0.f,0.f,0.f,0.f);
            if (gr < TN) v = *(const float4*)(xb + (size_t)gr*DD + q);
            *(float4*)(&xs[row][q]) = v;
        }
        __syncthreads();
        // logits: warp handles rows warp*8..warp*8+7, lane = e
        {
            float v[8];
            #pragma unroll
            for (int j = 0; j < 8; j++) v[j] = 0.f;
            #pragma unroll 4
            for (int k4 = 0; k4 < 16; k4++) {
                float4 ev = *(const float4*)&ec4[k4*128 + lane*4];
                #pragma unroll
                for (int j = 0; j < 8; j++) {
                    float4 xv = *(const float4*)&xs[warp*8 + j][k4*4];
                    v[j] = fmaf(xv.x, ev.x, v[j]);
                    v[j] = fmaf(xv.y, ev.y, v[j]);
                    v[j] = fmaf(xv.z, ev.z, v[j]);
                    v[j] = fmaf(xv.w, ev.w, v[j]);
                }
            }
            #pragma unroll
            for (int j = 0; j < 8; j++) {
                int r = warp*8 + j;
                int gr = r0 + r;
                float m = v[j];
                #pragma unroll
                for (int o = 16; o; o >>= 1) m = fmaxf(m, __shfl_xor_sync(0xffffffffu, m, o));
                float ex = __expf(v[j] - m);
                float sm = ex;
                #pragma unroll
                for (int o = 16; o; o >>= 1) sm += __shfl_xor_sync(0xffffffffu, sm, o);
                float p = ex / sm;
                bool valid = (gr < TN);
                as[r][lane] = valid ? p : 0.f;
                if (valid) assign[((size_t)b*TN + gr)*EE + lane] = p;
            }
        }
        __syncthreads();
        #pragma unroll 4
        for (int r = 0; r < 64; r++) {
            float a = as[r][e_own];
            float4 x0 = *(const float4*)&xs[r][dbase];
            float4 x1 = *(const float4*)&xs[r][dbase+4];
            acc[0] = fmaf(a, x0.x, acc[0]); acc[1] = fmaf(a, x0.y, acc[1]);
            acc[2] = fmaf(a, x0.z, acc[2]); acc[3] = fmaf(a, x0.w, acc[3]);
            acc[4] = fmaf(a, x1.x, acc[4]); acc[5] = fmaf(a, x1.y, acc[5]);
            acc[6] = fmaf(a, x1.z, acc[6]); acc[7] = fmaf(a, x1.w, acc[7]);
        }
    }
    float* hb = hf + b*EE*DD + e_own*DD + dbase;
    #pragma unroll
    for (int j = 0; j < 8; j++) atomicAdd(hb + j, acc[j]);
}

// ============================ K2: edge mix ============================
__global__ __launch_bounds__(256) void k_edge_mix(
    const float* __restrict__ hf, const float* __restrict__ edge_map,
    float* __restrict__ ho)
{
    __shared__ float hfs[32][64];
    __shared__ float em[32][32];
    int tid = threadIdx.x;
    int b = blockIdx.x;
    const float* hb = hf + b*EE*DD;
    for (int i = tid; i < 2048; i += 256) hfs[i>>6][i&63] = hb[i];
    for (int i = tid; i < 1024; i += 256) em[i>>5][i&31] = edge_map[i];
    __syncthreads();
    int e = tid >> 3, dbase = (tid & 7) * 8;
    float o[8];
    #pragma unroll
    for (int j = 0; j < 8; j++) o[j] = 0.f;
    #pragma unroll
    for (int f = 0; f < 32; f++) {
        float w = em[e][f];
        #pragma unroll
        for (int j = 0; j < 8; j++) o[j] = fmaf(w, hfs[f][dbase + j], o[j]);
    }
    float* ob = ho + b*EE*DD + e*DD + dbase;
    #pragma unroll
    for (int j = 0; j < 8; j++) ob[j] = fmaxf(o[j], 0.f) + hfs[e][dbase + j];
}

// ============================ K3: fused output ============================
// 8 warps/block, 8 rows/warp (register-tiled), lane owns column pair (2l, 2l+1)
#define K3_ROWS 64
#define K3_BLOCKS_PER_B ((TN + K3_ROWS - 1)/K3_ROWS)   // 135
#define K3_SMEM_FLOATS (8192 + 2048 + 384 + 4096 + 2048)

__global__ __launch_bounds__(256) void k_fused_out(
    const float* __restrict__ x,
    const float* __restrict__ W1, const float* __restrict__ b1,
    const float* __restrict__ W2, const float* __restrict__ b2,
    const float* __restrict__ ln1g, const float* __restrict__ ln1b,
    const float* __restrict__ ln2g, const float* __restrict__ ln2b,
    const float* __restrict__ assign, const float* __restrict__ ho,
    float* __restrict__ out)
{
    extern __shared__ float smem[];
    float* w4s = smem;              // [k][128]: (w1[k][2l],w1[k][2l+1],w2[k][2l],w2[k][2l+1])
    float* hos = w4s + 8192;        // [e][64]
    float* prm = hos + 2048;        // [6][64]
    float* xms = prm + 384;         // [warp][8][64]
    float* ass = xms + 4096;        // [warp][8][32]

    int tid = threadIdx.x;
    int b = blockIdx.x;
    int lane = tid & 31, warp = tid >> 5;

    for (int i = tid; i < 4096; i += 256) {
        int k = i >> 6, c = i & 63;
        int p = c >> 1, q = c & 1;
        w4s[k*128 + p*4 + q]     = W1[i];
        w4s[k*128 + p*4 + 2 + q] = W2[i];
    }
    for (int i = tid; i < 2048; i += 256) hos[i] = ho[b*EE*DD + i];
    if (tid < 64) {
        prm[0*64 + tid] = b1[tid];   prm[1*64 + tid] = b2[tid];
        prm[2*64 + tid] = ln1g[tid]; prm[3*64 + tid] = ln1b[tid];
        prm[4*64 + tid] = ln2g[tid]; prm[5*64 + tid] = ln2b[tid];
    }
    __syncthreads();

    int rowbase = blockIdx.y * K3_ROWS + warp * 8;
    const float* xb = x + (size_t)b*TN*DD;
    const float* ab = assign + (size_t)b*TN*EE;
    float* ob = out + (size_t)b*TN*DD;
    float* xmw = xms + warp*8*64;
    float* asw = ass + warp*8*32;

    // ---- prologue: load x pairs, compute windowed mean, stage assign ----
    float2 XV[8];
    #pragma unroll
    for (int r = 0; r < 8; r++) {
        int row = rowbase + r;
        float2 xv = make_float2(0.f, 0.f), xp = make_float2(0.f, 0.f);
        float a = 0.f;
        if (row < TN) {
            xv = *(const float2*)(xb + (size_t)row*DD + 2*lane);
            if (row >= NN) xp = *(const float2*)(xb + (size_t)(row - NN)*DD + 2*lane);
            a = ab[(size_t)row*EE + lane];
        }
        XV[r] = xv;
        float2 m = make_float2(0.5f*(xv.x + xp.x), 0.5f*(xv.y + xp.y));
        *(float2*)(xmw + r*64 + 2*lane) = m;
        asw[r*32 + lane] = a;
    }
    __syncwarp();

    // ---- main GEMVs via FFMA2, 8 rows per warp ----
    ull B1p = pack2(prm[0*64 + 2*lane], prm[0*64 + 2*lane + 1]);
    ull B2p = pack2(prm[1*64 + 2*lane], prm[1*64 + 2*lane + 1]);
    ull G1[8], G2[8];
    #pragma unroll
    for (int r = 0; r < 8; r++) { G1[r] = B1p; G2[r] = B2p; }

    #pragma unroll 2
    for (int k4 = 0; k4 < 16; k4++) {
        ulonglong2 wv0 = *(const ulonglong2*)&w4s[(4*k4+0)*128 + lane*4];
        ulonglong2 wv1 = *(const ulonglong2*)&w4s[(4*k4+1)*128 + lane*4];
        ulonglong2 wv2 = *(const ulonglong2*)&w4s[(4*k4+2)*128 + lane*4];
        ulonglong2 wv3 = *(const ulonglong2*)&w4s[(4*k4+3)*128 + lane*4];
        #pragma unroll
        for (int r = 0; r < 8; r++) {
            float4 mv = *(const float4*)(xmw + r*64 + 4*k4);
            ull m0 = packdup(mv.x), m1 = packdup(mv.y);
            ull m2 = packdup(mv.z), m3 = packdup(mv.w);
            G1[r] = fma2(wv0.x, m0, G1[r]); G2[r] = fma2(wv0.y, m0, G2[r]);
            G1[r] = fma2(wv1.x, m1, G1[r]); G2[r] = fma2(wv1.y, m1, G2[r]);
            G1[r] = fma2(wv2.x, m2, G1[r]); G2[r] = fma2(wv2.y, m2, G2[r]);
            G1[r] = fma2(wv3.x, m3, G1[r]); G2[r] = fma2(wv3.y, m3, G2[r]);
        }
    }

    // ---- hyper: Y = assign @ ho (pairs) ----
    ull Y[8];
    #pragma unroll
    for (int r = 0; r < 8; r++) Y[r] = 0ull;
    #pragma unroll 4
    for (int e2 = 0; e2 < 16; e2++) {
        float2 h0 = *(const float2*)(hos + (2*e2)*64 + 2*lane);
        float2 h1 = *(const float2*)(hos + (2*e2+1)*64 + 2*lane);
        ull H0 = pack2(h0.x, h0.y);
        ull H1 = pack2(h1.x, h1.y);
        #pragma unroll
        for (int r = 0; r < 8; r++) {
            float2 a2 = *(const float2*)(asw + r*32 + 2*e2);
            Y[r] = fma2(H0, packdup(a2.x), Y[r]);
            Y[r] = fma2(H1, packdup(a2.y), Y[r]);
        }
    }

    // ---- epilogue: gate + LN1, relu + LN2, average, store ----
    float g1w = prm[2*64 + 2*lane], g1w2 = prm[2*64 + 2*lane + 1];
    float b1w = prm[3*64 + 2*lane], b1w2 = prm[3*64 + 2*lane + 1];
    float g2w = prm[4*64 + 2*lane], g2w2 = prm[4*64 + 2*lane + 1];
    float b2w = prm[5*64 + 2*lane], b2w2 = prm[5*64 + 2*lane + 1];

    #pragma unroll
    for (int r = 0; r < 8; r++) {
        int row = rowbase + r;
        if (row >= TN) break;   // warp-uniform
        float g1a, g1b, g2a, g2b, y0, y1;
        unpack2(G1[r], g1a, g1b);
        unpack2(G2[r], g2a, g2b);
        unpack2(Y[r], y0, y1);
        float f0 = fmaxf(g1a*g2a, 0.f) + g1a + XV[r].x;
        float f1 = fmaxf(g1b*g2b, 0.f) + g1b + XV[r].y;
        float s = f0 + f1, s2 = f0*f0 + f1*f1;
        #pragma unroll
        for (int o = 16; o; o >>= 1) {
            s  += __shfl_xor_sync(0xffffffffu, s,  o);
            s2 += __shfl_xor_sync(0xffffffffu, s2, o);
        }
        float mu = s * (1.f/64.f);
        float var = s2 * (1.f/64.f) - mu*mu;
        float rs = rsqrtf(var + 1e-5f);
        float o1a = (f0 - mu)*rs*g1w + b1w;
        float o1b = (f1 - mu)*rs*g1w2 + b1w2;

        float h0 = fmaxf(y0, 0.f) + XV[r].x;
        float h1 = fmaxf(y1, 0.f) + XV[r].y;
        s = h0 + h1; s2 = h0*h0 + h1*h1;
        #pragma unroll
        for (int o = 16; o; o >>= 1) {
            s  += __shfl_xor_sync(0xffffffffu, s,  o);
            s2 += __shfl_xor_sync(0xffffffffu, s2, o);
        }
        mu = s * (1.f/64.f);
        var = s2 * (1.f/64.f) - mu*mu;
        rs = rsqrtf(var + 1e-5f);
        float o2a = (h0 - mu)*rs*g2w + b2w;
        float o2b = (h1 - mu)*rs*g2w2 + b2w2;

        float2 ov = make_float2(0.5f*(o1a + o2a), 0.5f*(o1b + o2b));
        *(float2*)(ob + (size_t)row*DD + 2*lane) = ov;
    }
}

extern "C" void kernel_launch(void* const* d_in, const int* in_sizes, int n_in,
                              void* d_out, int out_size) {
    const float* x    = (const float*)d_in[0];
    const float* W1   = (const float*)d_in[1];
    const float* b1   = (const float*)d_in[2];
    const float* W2   = (const float*)d_in[3];
    const float* b2   = (const float*)d_in[4];
    const float* ln1g = (const float*)d_in[5];
    const float* ln1b = (const float*)d_in[6];
    const float* eclf = (const float*)d_in[7];
    const float* emap = (const float*)d_in[8];
    const float* ln2g = (const float*)d_in[9];
    const float* ln2b = (const float*)d_in[10];

    float *bufA, *bufB, *assign, *hf, *ho;
    cudaGetSymbolAddress((void**)&bufA,   g_bufA);
    cudaGetSymbolAddress((void**)&bufB,   g_bufB);
    cudaGetSymbolAddress((void**)&assign, g_assign);
    cudaGetSymbolAddress((void**)&hf,     g_hf);
    cudaGetSymbolAddress((void**)&ho,     g_ho);

    static bool attr_set = false;
    cudaFuncSetAttribute(k_fused_out, cudaFuncAttributeMaxDynamicSharedMemorySize,
                         K3_SMEM_FLOATS * (int)sizeof(float));
    (void)attr_set;

    const float* cur = x;
    float* outs[3] = { bufA, bufB, (float*)d_out };

    for (int i = 0; i < 3; i++) {
        k_zero_hf<<<(BN*EE*DD + 255)/256, 256>>>(hf);
        dim3 g1(BN, K1_BLOCKS_PER_B);
        k_assign_hf<<<g1, 256>>>(cur, eclf, assign, hf);
        k_edge_mix<<<BN, 256>>>(hf, emap, ho);
        dim3 g3(BN, K3_BLOCKS_PER_B);
        k_fused_out<<<g3, 256, K3_SMEM_FLOATS * sizeof(float)>>>(
            cur, W1 + i*DD*DD, b1 + i*DD, W2 + i*DD*DD, b2 + i*DD,
            ln1g + i*DD, ln1b + i*DD, ln2g, ln2b,
            assign, ho, outs[i]);
        cur = outs[i];
    }
}